// round 14
// baseline (speedup 1.0000x reference)
#include <cuda_runtime.h>
#include <cuda_fp16.h>
#include <cstdint>

// C[2048,4096] = A[2048,4096] @ W[4096,4096]^T + bias
// W dequantized from 4-bit codebook codes.
// R14: R8 gemm mainloop (tile 128x128, BK=32, 3-stage cp.async, 2 CTAs/SM)
// + split-K=4 (grid.z) to kill wave quantization (6.92 -> 7 waves vs
// 1.73 -> 2), atomicAdd epilogue, C zeroed inside the prep kernel.

constexpr int KDIM = 4096;
constexpr int NDIM = 4096;
constexpr int MDIM = 2048;

__device__ __half g_W[(size_t)NDIM * KDIM];   // dequantized fp16
__device__ __half g_A[(size_t)MDIM * KDIM];   // activations fp16

// ---------------------------------------------------------------------------
// Phase 1: merged prep.
//   blocks [0, 4096):          dequant W rows
//   blocks [4096, 4608):       convert x -> fp16
//   blocks [4608, 5120):       zero C (d_out is poisoned; epilogue is atomic)
// ---------------------------------------------------------------------------
constexpr int ACONV_BLOCKS = 512;
constexpr int ZERO_BLOCKS  = 512;
constexpr int ACHUNKS = MDIM * KDIM / 4;      // float4 chunks of x
constexpr int CCHUNKS = MDIM * NDIM / 4;      // float4 chunks of C

__global__ void prep_kernel(const float* __restrict__ codebooks,
                            const int* __restrict__ codes,
                            const float* __restrict__ x,
                            float* __restrict__ C) {
    if (blockIdx.x < NDIM) {
        const int r = blockIdx.x;
        __shared__ float cb[512];
        const float* cbr = codebooks + (size_t)r * 512;
        for (int i = threadIdx.x; i < 512; i += 256) cb[i] = cbr[i];
        __syncthreads();

        const int4* codes_r = (const int4*)(codes + (size_t)r * KDIM);
        __half2* w2 = (__half2*)(g_W + (size_t)r * KDIM);
        #pragma unroll
        for (int it = 0; it < 4; it++) {
            int i = threadIdx.x + it * 256;
            int4 c = codes_r[i];
            const float* cbg = cb + ((i >> 5) << 4);
            w2[2 * i]     = __floats2half2_rn(cbg[c.x], cbg[c.y]);
            w2[2 * i + 1] = __floats2half2_rn(cbg[c.z], cbg[c.w]);
        }
    } else if (blockIdx.x < NDIM + ACONV_BLOCKS) {
        const int b = blockIdx.x - NDIM;
        __half2* a2 = (__half2*)g_A;
        #pragma unroll
        for (int it = 0; it < ACHUNKS / (ACONV_BLOCKS * 256); it++) {
            size_t i = (size_t)it * ACONV_BLOCKS * 256 + (size_t)b * 256 + threadIdx.x;
            const float4 v = ((const float4*)x)[i];
            a2[2 * i]     = __floats2half2_rn(v.x, v.y);
            a2[2 * i + 1] = __floats2half2_rn(v.z, v.w);
        }
    } else {
        const int b = blockIdx.x - NDIM - ACONV_BLOCKS;
        float4* c4 = (float4*)C;
        const float4 z = make_float4(0.f, 0.f, 0.f, 0.f);
        #pragma unroll
        for (int it = 0; it < CCHUNKS / (ZERO_BLOCKS * 256); it++) {
            size_t i = (size_t)it * ZERO_BLOCKS * 256 + (size_t)b * 256 + threadIdx.x;
            c4[i] = z;
        }
    }
}

// ---------------------------------------------------------------------------
// Phase 2: fp16 mma.sync GEMM. Block 128x128, K-split 4 (1024 each),
// BK=32, 4 warps, warp tile 64x64, 3-stage cp.async (wait_group 1),
// ldmatrix, 2 CTAs/SM, atomic epilogue.
// ---------------------------------------------------------------------------
constexpr int BM = 128, BN = 128, BK = 32;
constexpr int KSPLIT = 4;
constexpr int KPB = KDIM / KSPLIT;                    // 1024 per block
constexpr int NTHREADS = 128;
constexpr int STRIDE = 40;                            // halfs; bank-bijective
constexpr int A_STAGE = BM * STRIDE;                  // 5120 halfs
constexpr int B_STAGE = BN * STRIDE;                  // 5120 halfs
constexpr int STAGE   = A_STAGE + B_STAGE;            // 10240 halfs (20480 B)
constexpr int NSTAGE  = 3;
constexpr int SMEM_DYN = STAGE * NSTAGE * 2;          // 61440 bytes
constexpr int KITERS = KPB / BK;                      // 32

extern __shared__ __half smh[];

__device__ __forceinline__ uint32_t smem_u32(const void* p) {
    uint32_t a;
    asm("{ .reg .u64 t; cvta.to.shared.u64 t, %1; cvt.u32.u64 %0, t; }"
        : "=r"(a) : "l"(p));
    return a;
}

__device__ __forceinline__ void cp_async16(uint32_t dst, const void* src) {
    asm volatile("cp.async.cg.shared.global [%0], [%1], 16;"
                 :: "r"(dst), "l"(src));
}

__device__ __forceinline__ void ldmatrix_x4(uint32_t* r, uint32_t addr) {
    asm volatile(
        "ldmatrix.sync.aligned.m8n8.x4.shared.b16 {%0, %1, %2, %3}, [%4];"
        : "=r"(r[0]), "=r"(r[1]), "=r"(r[2]), "=r"(r[3])
        : "r"(addr));
}

__device__ __forceinline__ void mma_f16(float* c, const uint32_t* a,
                                        const uint32_t* b) {
    asm volatile(
        "mma.sync.aligned.m16n8k16.row.col.f32.f16.f16.f32 "
        "{%0,%1,%2,%3}, {%4,%5,%6,%7}, {%8,%9}, {%0,%1,%2,%3};"
        : "+f"(c[0]), "+f"(c[1]), "+f"(c[2]), "+f"(c[3])
        : "r"(a[0]), "r"(a[1]), "r"(a[2]), "r"(a[3]), "r"(b[0]), "r"(b[1]));
}

__device__ __forceinline__ void load_tile(uint32_t sbase,
                                          const __half* __restrict__ Ab,
                                          const __half* __restrict__ Bb,
                                          int k0, int tid) {
    // A: 128 rows x 4 chunks(8 halfs) = 512; 4 per thread
    #pragma unroll
    for (int j = 0; j < 4; j++) {
        int i = tid + j * NTHREADS;
        int row = i >> 2, c = (i & 3) * 8;
        cp_async16(sbase + (uint32_t)(row * STRIDE + c) * 2,
                   Ab + (size_t)row * KDIM + k0 + c);
    }
    // B: 128 rows x 4 chunks = 512; 4 per thread
    const uint32_t sb = sbase + A_STAGE * 2;
    #pragma unroll
    for (int j = 0; j < 4; j++) {
        int i = tid + j * NTHREADS;
        int row = i >> 2, c = (i & 3) * 8;
        cp_async16(sb + (uint32_t)(row * STRIDE + c) * 2,
                   Bb + (size_t)row * KDIM + k0 + c);
    }
    asm volatile("cp.async.commit_group;" ::: "memory");
}

__global__ void __launch_bounds__(NTHREADS, 2)
gemm_mma_kernel(const float* __restrict__ bias, float* __restrict__ C) {
    const int tid  = threadIdx.x;
    const int wid  = tid >> 5;
    const int lane = tid & 31;
    const int gid  = lane >> 2;      // group of 4
    const int tig  = lane & 3;       // thread in group

    const int m0 = blockIdx.y * BM;
    const int n0 = blockIdx.x * BN;
    const int kz = blockIdx.z;       // K-split index
    const int wm = (wid >> 1) * 64;  // warp grid 2(M) x 2(N), tile 64x64
    const int wn = (wid & 1) * 64;

    const uint32_t smem_base = smem_u32(smh);
    const __half* Ab = g_A + (size_t)m0 * KDIM + kz * KPB;
    const __half* Bb = g_W + (size_t)n0 * KDIM + kz * KPB;

    // ldmatrix per-lane address offsets (bytes)
    const uint32_t a_lane = (uint32_t)((lane & 15) * STRIDE + ((lane >> 4) << 3)) * 2;
    const uint32_t b_lane = (uint32_t)((((lane >> 4) << 3) + (lane & 7)) * STRIDE
                                       + (lane & 8)) * 2;

    float acc[4][8][4] = {};

    load_tile(smem_base,             Ab, Bb, 0,  tid);
    load_tile(smem_base + STAGE * 2, Ab, Bb, BK, tid);

    for (int it = 0; it < KITERS; it++) {
        if (it + 1 < KITERS) {
            asm volatile("cp.async.wait_group 1;" ::: "memory");
        } else {
            asm volatile("cp.async.wait_group 0;" ::: "memory");
        }
        __syncthreads();

        if (it + 2 < KITERS) {
            load_tile(smem_base + (uint32_t)((it + 2) % NSTAGE) * STAGE * 2,
                      Ab, Bb, (it + 2) * BK, tid);
        }

        const uint32_t sA = smem_base + (uint32_t)(it % NSTAGE) * STAGE * 2;
        const uint32_t sB = sA + A_STAGE * 2;

        #pragma unroll
        for (int ks = 0; ks < 2; ks++) {            // 2 x K=16 steps
            const int kb = ks * 16;
            uint32_t af[4][4], bf[4][4];            // bf[p] covers nt=2p,2p+1
            #pragma unroll
            for (int mt = 0; mt < 4; mt++) {
                ldmatrix_x4(af[mt],
                            sA + (uint32_t)((wm + mt * 16) * STRIDE + kb) * 2
                               + a_lane);
            }
            #pragma unroll
            for (int p = 0; p < 4; p++) {
                ldmatrix_x4(bf[p],
                            sB + (uint32_t)((wn + p * 16) * STRIDE + kb) * 2
                               + b_lane);
            }
            #pragma unroll
            for (int mt = 0; mt < 4; mt++) {
                #pragma unroll
                for (int p = 0; p < 4; p++) {
                    mma_f16(acc[mt][2 * p],     af[mt], &bf[p][0]);
                    mma_f16(acc[mt][2 * p + 1], af[mt], &bf[p][2]);
                }
            }
        }
    }

    // epilogue: atomic accumulate (C pre-zeroed); split 0 contributes bias
    const float bsel = (kz == 0) ? 1.0f : 0.0f;
    #pragma unroll
    for (int mt = 0; mt < 4; mt++) {
        #pragma unroll
        for (int nt = 0; nt < 8; nt++) {
            const int r0 = m0 + wm + mt * 16 + gid;
            const int c  = n0 + wn + nt * 8 + tig * 2;
            const float2 b2 = *(const float2*)(bias + c);
            float* p0 = C + (size_t)r0 * NDIM + c;
            float* p1 = C + (size_t)(r0 + 8) * NDIM + c;
            atomicAdd(p0,     acc[mt][nt][0] + bsel * b2.x);
            atomicAdd(p0 + 1, acc[mt][nt][1] + bsel * b2.y);
            atomicAdd(p1,     acc[mt][nt][2] + bsel * b2.x);
            atomicAdd(p1 + 1, acc[mt][nt][3] + bsel * b2.y);
        }
    }
}

// ---------------------------------------------------------------------------
extern "C" void kernel_launch(void* const* d_in, const int* in_sizes, int n_in,
                              void* d_out, int out_size) {
    const float* x         = (const float*)d_in[0];
    const float* codebooks = (const float*)d_in[1];
    const int*   codes     = (const int*)d_in[2];
    const float* bias      = (const float*)d_in[3];
    float* out = (float*)d_out;

    prep_kernel<<<NDIM + ACONV_BLOCKS + ZERO_BLOCKS, 256>>>(codebooks, codes,
                                                            x, out);

    cudaFuncSetAttribute(gemm_mma_kernel,
                         cudaFuncAttributeMaxDynamicSharedMemorySize, SMEM_DYN);
    dim3 grid(NDIM / BN, MDIM / BM, KSPLIT);   // (32, 16, 4) = 2048 blocks
    gemm_mma_kernel<<<grid, NTHREADS, SMEM_DYN>>>(bias, out);
}

// round 15
// speedup vs baseline: 1.0086x; 1.0086x over previous
#include <cuda_runtime.h>
#include <cuda_fp16.h>
#include <cstdint>

// C[2048,4096] = A[2048,4096] @ W[4096,4096]^T + bias
// W dequantized from 4-bit codebook codes.
// R15: split-K=4 (kills 1.73->2 wave quantization) with a VECTORIZED atomic
// epilogue: shfl_xor lane-pairing -> red.global.add.v4.f32 (32 ops/thread vs
// R14's 128 scalar). Bias pre-initialized into C by the prep kernel.

constexpr int KDIM = 4096;
constexpr int NDIM = 4096;
constexpr int MDIM = 2048;

__device__ __half g_W[(size_t)NDIM * KDIM];   // dequantized fp16
__device__ __half g_A[(size_t)MDIM * KDIM];   // activations fp16

// ---------------------------------------------------------------------------
// Phase 1: merged prep.
//   blocks [0, 4096):        dequant W rows
//   blocks [4096, 4608):     convert x -> fp16
//   blocks [4608, 5120):     init C with broadcast bias (epilogue is atomic)
// ---------------------------------------------------------------------------
constexpr int ACONV_BLOCKS = 512;
constexpr int INIT_BLOCKS  = 512;
constexpr int ACHUNKS = MDIM * KDIM / 4;      // float4 chunks of x
constexpr int CCHUNKS = MDIM * NDIM / 4;      // float4 chunks of C

__global__ void prep_kernel(const float* __restrict__ codebooks,
                            const int* __restrict__ codes,
                            const float* __restrict__ x,
                            const float* __restrict__ bias,
                            float* __restrict__ C) {
    if (blockIdx.x < NDIM) {
        const int r = blockIdx.x;
        __shared__ float cb[512];
        const float* cbr = codebooks + (size_t)r * 512;
        for (int i = threadIdx.x; i < 512; i += 256) cb[i] = cbr[i];
        __syncthreads();

        const int4* codes_r = (const int4*)(codes + (size_t)r * KDIM);
        __half2* w2 = (__half2*)(g_W + (size_t)r * KDIM);
        #pragma unroll
        for (int it = 0; it < 4; it++) {
            int i = threadIdx.x + it * 256;
            int4 c = codes_r[i];
            const float* cbg = cb + ((i >> 5) << 4);
            w2[2 * i]     = __floats2half2_rn(cbg[c.x], cbg[c.y]);
            w2[2 * i + 1] = __floats2half2_rn(cbg[c.z], cbg[c.w]);
        }
    } else if (blockIdx.x < NDIM + ACONV_BLOCKS) {
        const int b = blockIdx.x - NDIM;
        __half2* a2 = (__half2*)g_A;
        #pragma unroll
        for (int it = 0; it < ACHUNKS / (ACONV_BLOCKS * 256); it++) {
            size_t i = (size_t)it * ACONV_BLOCKS * 256 + (size_t)b * 256 + threadIdx.x;
            const float4 v = ((const float4*)x)[i];
            a2[2 * i]     = __floats2half2_rn(v.x, v.y);
            a2[2 * i + 1] = __floats2half2_rn(v.z, v.w);
        }
    } else {
        const int b = blockIdx.x - NDIM - ACONV_BLOCKS;
        float4* c4 = (float4*)C;
        const float4* b4 = (const float4*)bias;   // 1024 float4 per row
        #pragma unroll
        for (int it = 0; it < CCHUNKS / (INIT_BLOCKS * 256); it++) {
            size_t i = (size_t)it * INIT_BLOCKS * 256 + (size_t)b * 256 + threadIdx.x;
            c4[i] = b4[i & 1023];
        }
    }
}

// ---------------------------------------------------------------------------
// Phase 2: fp16 mma.sync GEMM. Block 128x128, K-split 4 (1024 each),
// BK=32, 4 warps, warp tile 64x64, 3-stage cp.async (wait_group 1),
// ldmatrix, 2 CTAs/SM, red.v4 epilogue.
// ---------------------------------------------------------------------------
constexpr int BM = 128, BN = 128, BK = 32;
constexpr int KSPLIT = 4;
constexpr int KPB = KDIM / KSPLIT;                    // 1024 per block
constexpr int NTHREADS = 128;
constexpr int STRIDE = 40;                            // halfs; bank-bijective
constexpr int A_STAGE = BM * STRIDE;                  // 5120 halfs
constexpr int B_STAGE = BN * STRIDE;                  // 5120 halfs
constexpr int STAGE   = A_STAGE + B_STAGE;            // 10240 halfs (20480 B)
constexpr int NSTAGE  = 3;
constexpr int SMEM_DYN = STAGE * NSTAGE * 2;          // 61440 bytes
constexpr int KITERS = KPB / BK;                      // 32

extern __shared__ __half smh[];

__device__ __forceinline__ uint32_t smem_u32(const void* p) {
    uint32_t a;
    asm("{ .reg .u64 t; cvta.to.shared.u64 t, %1; cvt.u32.u64 %0, t; }"
        : "=r"(a) : "l"(p));
    return a;
}

__device__ __forceinline__ void cp_async16(uint32_t dst, const void* src) {
    asm volatile("cp.async.cg.shared.global [%0], [%1], 16;"
                 :: "r"(dst), "l"(src));
}

__device__ __forceinline__ void ldmatrix_x4(uint32_t* r, uint32_t addr) {
    asm volatile(
        "ldmatrix.sync.aligned.m8n8.x4.shared.b16 {%0, %1, %2, %3}, [%4];"
        : "=r"(r[0]), "=r"(r[1]), "=r"(r[2]), "=r"(r[3])
        : "r"(addr));
}

__device__ __forceinline__ void mma_f16(float* c, const uint32_t* a,
                                        const uint32_t* b) {
    asm volatile(
        "mma.sync.aligned.m16n8k16.row.col.f32.f16.f16.f32 "
        "{%0,%1,%2,%3}, {%4,%5,%6,%7}, {%8,%9}, {%0,%1,%2,%3};"
        : "+f"(c[0]), "+f"(c[1]), "+f"(c[2]), "+f"(c[3])
        : "r"(a[0]), "r"(a[1]), "r"(a[2]), "r"(a[3]), "r"(b[0]), "r"(b[1]));
}

__device__ __forceinline__ void red4(float* p, float a, float b,
                                     float c, float d) {
    asm volatile("red.global.add.v4.f32 [%0], {%1, %2, %3, %4};"
                 :: "l"(p), "f"(a), "f"(b), "f"(c), "f"(d) : "memory");
}

__device__ __forceinline__ void load_tile(uint32_t sbase,
                                          const __half* __restrict__ Ab,
                                          const __half* __restrict__ Bb,
                                          int k0, int tid) {
    // A: 128 rows x 4 chunks(8 halfs) = 512; 4 per thread
    #pragma unroll
    for (int j = 0; j < 4; j++) {
        int i = tid + j * NTHREADS;
        int row = i >> 2, c = (i & 3) * 8;
        cp_async16(sbase + (uint32_t)(row * STRIDE + c) * 2,
                   Ab + (size_t)row * KDIM + k0 + c);
    }
    // B: 128 rows x 4 chunks = 512; 4 per thread
    const uint32_t sb = sbase + A_STAGE * 2;
    #pragma unroll
    for (int j = 0; j < 4; j++) {
        int i = tid + j * NTHREADS;
        int row = i >> 2, c = (i & 3) * 8;
        cp_async16(sb + (uint32_t)(row * STRIDE + c) * 2,
                   Bb + (size_t)row * KDIM + k0 + c);
    }
    asm volatile("cp.async.commit_group;" ::: "memory");
}

__global__ void __launch_bounds__(NTHREADS, 2)
gemm_mma_kernel(float* __restrict__ C) {
    const int tid  = threadIdx.x;
    const int wid  = tid >> 5;
    const int lane = tid & 31;
    const int gid  = lane >> 2;      // group of 4
    const int tig  = lane & 3;       // thread in group

    const int m0 = blockIdx.y * BM;
    const int n0 = blockIdx.x * BN;
    const int kz = blockIdx.z;       // K-split index
    const int wm = (wid >> 1) * 64;  // warp grid 2(M) x 2(N), tile 64x64
    const int wn = (wid & 1) * 64;

    const uint32_t smem_base = smem_u32(smh);
    const __half* Ab = g_A + (size_t)m0 * KDIM + kz * KPB;
    const __half* Bb = g_W + (size_t)n0 * KDIM + kz * KPB;

    // ldmatrix per-lane address offsets (bytes)
    const uint32_t a_lane = (uint32_t)((lane & 15) * STRIDE + ((lane >> 4) << 3)) * 2;
    const uint32_t b_lane = (uint32_t)((((lane >> 4) << 3) + (lane & 7)) * STRIDE
                                       + (lane & 8)) * 2;

    float acc[4][8][4] = {};

    load_tile(smem_base,             Ab, Bb, 0,  tid);
    load_tile(smem_base + STAGE * 2, Ab, Bb, BK, tid);

    for (int it = 0; it < KITERS; it++) {
        if (it + 1 < KITERS) {
            asm volatile("cp.async.wait_group 1;" ::: "memory");
        } else {
            asm volatile("cp.async.wait_group 0;" ::: "memory");
        }
        __syncthreads();

        if (it + 2 < KITERS) {
            load_tile(smem_base + (uint32_t)((it + 2) % NSTAGE) * STAGE * 2,
                      Ab, Bb, (it + 2) * BK, tid);
        }

        const uint32_t sA = smem_base + (uint32_t)(it % NSTAGE) * STAGE * 2;
        const uint32_t sB = sA + A_STAGE * 2;

        #pragma unroll
        for (int ks = 0; ks < 2; ks++) {            // 2 x K=16 steps
            const int kb = ks * 16;
            uint32_t af[4][4], bf[4][4];            // bf[p] covers nt=2p,2p+1
            #pragma unroll
            for (int mt = 0; mt < 4; mt++) {
                ldmatrix_x4(af[mt],
                            sA + (uint32_t)((wm + mt * 16) * STRIDE + kb) * 2
                               + a_lane);
            }
            #pragma unroll
            for (int p = 0; p < 4; p++) {
                ldmatrix_x4(bf[p],
                            sB + (uint32_t)((wn + p * 16) * STRIDE + kb) * 2
                               + b_lane);
            }
            #pragma unroll
            for (int mt = 0; mt < 4; mt++) {
                #pragma unroll
                for (int p = 0; p < 4; p++) {
                    mma_f16(acc[mt][2 * p],     af[mt], &bf[p][0]);
                    mma_f16(acc[mt][2 * p + 1], af[mt], &bf[p][2]);
                }
            }
        }
    }

    // epilogue: lane-pair shuffle -> one red.v4 per (mt,nt) per lane.
    // Even tig lanes write row r0 (own v0,v1 + partner v0,v1);
    // odd tig lanes write row r0+8 at partner's column base.
    #pragma unroll
    for (int mt = 0; mt < 4; mt++) {
        #pragma unroll
        for (int nt = 0; nt < 8; nt++) {
            const int r0 = m0 + wm + mt * 16 + gid;
            const int c  = n0 + wn + nt * 8 + tig * 2;
            float v0 = acc[mt][nt][0], v1 = acc[mt][nt][1];
            float v2 = acc[mt][nt][2], v3 = acc[mt][nt][3];
            float w0 = __shfl_xor_sync(0xffffffffu, v0, 1);
            float w1 = __shfl_xor_sync(0xffffffffu, v1, 1);
            float w2 = __shfl_xor_sync(0xffffffffu, v2, 1);
            float w3 = __shfl_xor_sync(0xffffffffu, v3, 1);
            if ((tig & 1) == 0) {
                red4(C + (size_t)r0 * NDIM + c, v0, v1, w0, w1);
            } else {
                red4(C + (size_t)(r0 + 8) * NDIM + (c - 2), w2, w3, v2, v3);
            }
        }
    }
}

// ---------------------------------------------------------------------------
extern "C" void kernel_launch(void* const* d_in, const int* in_sizes, int n_in,
                              void* d_out, int out_size) {
    const float* x         = (const float*)d_in[0];
    const float* codebooks = (const float*)d_in[1];
    const int*   codes     = (const int*)d_in[2];
    const float* bias      = (const float*)d_in[3];
    float* out = (float*)d_out;

    prep_kernel<<<NDIM + ACONV_BLOCKS + INIT_BLOCKS, 256>>>(codebooks, codes,
                                                            x, bias, out);

    cudaFuncSetAttribute(gemm_mma_kernel,
                         cudaFuncAttributeMaxDynamicSharedMemorySize, SMEM_DYN);
    dim3 grid(NDIM / BN, MDIM / BM, KSPLIT);   // (32, 16, 4) = 2048 blocks
    gemm_mma_kernel<<<grid, NTHREADS, SMEM_DYN>>>(out);
}

// round 16
// speedup vs baseline: 1.0634x; 1.0544x over previous
#include <cuda_runtime.h>
#include <cuda_fp16.h>
#include <cstdint>

// C[2048,4096] = A[2048,4096] @ W[4096,4096]^T + bias
// W dequantized from 4-bit codebook codes.
// R16: R8 gemm verbatim (tile 128x128, BK=32, 3-stage cp.async wait_group 1,
// 4 warps 64x64 tiles, 2 CTAs/SM, direct bias epilogue) + restructured
// dequant: 16 codes/thread, front-batched LDG.128 x4, STG.128 x2.

constexpr int KDIM = 4096;
constexpr int NDIM = 4096;
constexpr int MDIM = 2048;

__device__ __half g_W[(size_t)NDIM * KDIM];   // dequantized fp16
__device__ __half g_A[(size_t)MDIM * KDIM];   // activations fp16

// ---------------------------------------------------------------------------
// Phase 1: merged prep. Blocks [0,4096): dequant W row. Blocks [4096,4608):
// convert x -> fp16.
// ---------------------------------------------------------------------------
constexpr int ACONV_BLOCKS = 512;
constexpr int ACHUNKS = MDIM * KDIM / 4;      // float4 chunks of x

__global__ void prep_kernel(const float* __restrict__ codebooks,
                            const int* __restrict__ codes,
                            const float* __restrict__ x) {
    if (blockIdx.x < NDIM) {
        const int r = blockIdx.x;
        const int t = threadIdx.x;
        __shared__ float cb[512];
        const float* cbr = codebooks + (size_t)r * 512;
        for (int i = t; i < 512; i += 256) cb[i] = cbr[i];
        __syncthreads();

        // Thread t owns elements [16t, 16t+16) of the row: exactly within
        // one codebook group (group = t/8). Batch all 4 LDG.128 first.
        const int4* cr = (const int4*)(codes + (size_t)r * KDIM);
        int4 c0 = cr[t * 4 + 0];
        int4 c1 = cr[t * 4 + 1];
        int4 c2 = cr[t * 4 + 2];
        int4 c3 = cr[t * 4 + 3];
        const float* cbg = cb + ((t >> 3) << 4);

        __half2 h[8];
        h[0] = __floats2half2_rn(cbg[c0.x], cbg[c0.y]);
        h[1] = __floats2half2_rn(cbg[c0.z], cbg[c0.w]);
        h[2] = __floats2half2_rn(cbg[c1.x], cbg[c1.y]);
        h[3] = __floats2half2_rn(cbg[c1.z], cbg[c1.w]);
        h[4] = __floats2half2_rn(cbg[c2.x], cbg[c2.y]);
        h[5] = __floats2half2_rn(cbg[c2.z], cbg[c2.w]);
        h[6] = __floats2half2_rn(cbg[c3.x], cbg[c3.y]);
        h[7] = __floats2half2_rn(cbg[c3.z], cbg[c3.w]);

        uint4* w4 = (uint4*)(g_W + (size_t)r * KDIM);
        w4[t * 2 + 0] = *(const uint4*)(&h[0]);
        w4[t * 2 + 1] = *(const uint4*)(&h[4]);
    } else {
        const int b = blockIdx.x - NDIM;
        __half2* a2 = (__half2*)g_A;
        #pragma unroll
        for (int it = 0; it < ACHUNKS / (ACONV_BLOCKS * 256); it++) {
            size_t i = (size_t)it * ACONV_BLOCKS * 256 + (size_t)b * 256 + threadIdx.x;
            const float4 v = ((const float4*)x)[i];
            a2[2 * i]     = __floats2half2_rn(v.x, v.y);
            a2[2 * i + 1] = __floats2half2_rn(v.z, v.w);
        }
    }
}

// ---------------------------------------------------------------------------
// Phase 2: fp16 mma.sync GEMM. Block 128x128x32(halfs), 4 warps,
// warp tile 64x64, 3-stage cp.async (wait_group 1), ldmatrix, 2 CTAs/SM.
// ---------------------------------------------------------------------------
constexpr int BM = 128, BN = 128, BK = 32;
constexpr int NTHREADS = 128;
constexpr int STRIDE = 40;                            // halfs; bank-bijective
constexpr int A_STAGE = BM * STRIDE;                  // 5120 halfs
constexpr int B_STAGE = BN * STRIDE;                  // 5120 halfs
constexpr int STAGE   = A_STAGE + B_STAGE;            // 10240 halfs (20480 B)
constexpr int NSTAGE  = 3;
constexpr int SMEM_DYN = STAGE * NSTAGE * 2;          // 61440 bytes
constexpr int KITERS = KDIM / BK;                     // 128

extern __shared__ __half smh[];

__device__ __forceinline__ uint32_t smem_u32(const void* p) {
    uint32_t a;
    asm("{ .reg .u64 t; cvta.to.shared.u64 t, %1; cvt.u32.u64 %0, t; }"
        : "=r"(a) : "l"(p));
    return a;
}

__device__ __forceinline__ void cp_async16(uint32_t dst, const void* src) {
    asm volatile("cp.async.cg.shared.global [%0], [%1], 16;"
                 :: "r"(dst), "l"(src));
}

__device__ __forceinline__ void ldmatrix_x4(uint32_t* r, uint32_t addr) {
    asm volatile(
        "ldmatrix.sync.aligned.m8n8.x4.shared.b16 {%0, %1, %2, %3}, [%4];"
        : "=r"(r[0]), "=r"(r[1]), "=r"(r[2]), "=r"(r[3])
        : "r"(addr));
}

__device__ __forceinline__ void mma_f16(float* c, const uint32_t* a,
                                        const uint32_t* b) {
    asm volatile(
        "mma.sync.aligned.m16n8k16.row.col.f32.f16.f16.f32 "
        "{%0,%1,%2,%3}, {%4,%5,%6,%7}, {%8,%9}, {%0,%1,%2,%3};"
        : "+f"(c[0]), "+f"(c[1]), "+f"(c[2]), "+f"(c[3])
        : "r"(a[0]), "r"(a[1]), "r"(a[2]), "r"(a[3]), "r"(b[0]), "r"(b[1]));
}

__device__ __forceinline__ void load_tile(uint32_t sbase,
                                          const __half* __restrict__ Ab,
                                          const __half* __restrict__ Bb,
                                          int k0, int tid) {
    // A: 128 rows x 4 chunks(8 halfs) = 512; 4 per thread
    #pragma unroll
    for (int j = 0; j < 4; j++) {
        int i = tid + j * NTHREADS;
        int row = i >> 2, c = (i & 3) * 8;
        cp_async16(sbase + (uint32_t)(row * STRIDE + c) * 2,
                   Ab + (size_t)row * KDIM + k0 + c);
    }
    // B: 128 rows x 4 chunks = 512; 4 per thread
    const uint32_t sb = sbase + A_STAGE * 2;
    #pragma unroll
    for (int j = 0; j < 4; j++) {
        int i = tid + j * NTHREADS;
        int row = i >> 2, c = (i & 3) * 8;
        cp_async16(sb + (uint32_t)(row * STRIDE + c) * 2,
                   Bb + (size_t)row * KDIM + k0 + c);
    }
    asm volatile("cp.async.commit_group;" ::: "memory");
}

__global__ void __launch_bounds__(NTHREADS, 2)
gemm_mma_kernel(const float* __restrict__ bias, float* __restrict__ C) {
    const int tid  = threadIdx.x;
    const int wid  = tid >> 5;
    const int lane = tid & 31;
    const int gid  = lane >> 2;      // group of 4
    const int tig  = lane & 3;       // thread in group

    const int m0 = blockIdx.y * BM;
    const int n0 = blockIdx.x * BN;
    const int wm = (wid >> 1) * 64;  // warp grid 2(M) x 2(N), tile 64x64
    const int wn = (wid & 1) * 64;

    const uint32_t smem_base = smem_u32(smh);
    const __half* Ab = g_A + (size_t)m0 * KDIM;
    const __half* Bb = g_W + (size_t)n0 * KDIM;

    // ldmatrix per-lane address offsets (bytes)
    const uint32_t a_lane = (uint32_t)((lane & 15) * STRIDE + ((lane >> 4) << 3)) * 2;
    const uint32_t b_lane = (uint32_t)((((lane >> 4) << 3) + (lane & 7)) * STRIDE
                                       + (lane & 8)) * 2;

    float acc[4][8][4] = {};

    load_tile(smem_base,             Ab, Bb, 0,  tid);
    load_tile(smem_base + STAGE * 2, Ab, Bb, BK, tid);

    for (int it = 0; it < KITERS; it++) {
        if (it + 1 < KITERS) {
            asm volatile("cp.async.wait_group 1;" ::: "memory");
        } else {
            asm volatile("cp.async.wait_group 0;" ::: "memory");
        }
        __syncthreads();

        if (it + 2 < KITERS) {
            load_tile(smem_base + (uint32_t)((it + 2) % NSTAGE) * STAGE * 2,
                      Ab, Bb, (it + 2) * BK, tid);
        }

        const uint32_t sA = smem_base + (uint32_t)(it % NSTAGE) * STAGE * 2;
        const uint32_t sB = sA + A_STAGE * 2;

        #pragma unroll
        for (int ks = 0; ks < 2; ks++) {            // 2 x K=16 steps
            const int kb = ks * 16;
            uint32_t af[4][4], bf[4][4];            // bf[p] covers nt=2p,2p+1
            #pragma unroll
            for (int mt = 0; mt < 4; mt++) {
                ldmatrix_x4(af[mt],
                            sA + (uint32_t)((wm + mt * 16) * STRIDE + kb) * 2
                               + a_lane);
            }
            #pragma unroll
            for (int p = 0; p < 4; p++) {
                ldmatrix_x4(bf[p],
                            sB + (uint32_t)((wn + p * 16) * STRIDE + kb) * 2
                               + b_lane);
            }
            #pragma unroll
            for (int mt = 0; mt < 4; mt++) {
                #pragma unroll
                for (int p = 0; p < 4; p++) {
                    mma_f16(acc[mt][2 * p],     af[mt], &bf[p][0]);
                    mma_f16(acc[mt][2 * p + 1], af[mt], &bf[p][2]);
                }
            }
        }
    }

    // epilogue: bias + store
    #pragma unroll
    for (int mt = 0; mt < 4; mt++) {
        #pragma unroll
        for (int nt = 0; nt < 8; nt++) {
            const int r0 = m0 + wm + mt * 16 + gid;
            const int c  = n0 + wn + nt * 8 + tig * 2;
            const float2 b2 = *(const float2*)(bias + c);
            float2 o0, o1;
            o0.x = acc[mt][nt][0] + b2.x;
            o0.y = acc[mt][nt][1] + b2.y;
            o1.x = acc[mt][nt][2] + b2.x;
            o1.y = acc[mt][nt][3] + b2.y;
            *(float2*)(C + (size_t)r0 * NDIM + c)       = o0;
            *(float2*)(C + (size_t)(r0 + 8) * NDIM + c) = o1;
        }
    }
}

// ---------------------------------------------------------------------------
extern "C" void kernel_launch(void* const* d_in, const int* in_sizes, int n_in,
                              void* d_out, int out_size) {
    const float* x         = (const float*)d_in[0];
    const float* codebooks = (const float*)d_in[1];
    const int*   codes     = (const int*)d_in[2];
    const float* bias      = (const float*)d_in[3];
    float* out = (float*)d_out;

    prep_kernel<<<NDIM + ACONV_BLOCKS, 256>>>(codebooks, codes, x);

    cudaFuncSetAttribute(gemm_mma_kernel,
                         cudaFuncAttributeMaxDynamicSharedMemorySize, SMEM_DYN);
    dim3 grid(NDIM / BN, MDIM / BM);   // (32, 16) = 512 blocks
    gemm_mma_kernel<<<grid, NTHREADS, SMEM_DYN>>>(bias, out);
}